// round 8
// baseline (speedup 1.0000x reference)
#include <cuda_runtime.h>

#define NN   100000
#define EE   1600000
#define CINF 16
#define HIDF 64
#define NG   192      // 3 live gates (i, f, o) x 64
#define KF   32       // feature dim: [x(16) | tx1(16)]
#define CAP  64       // bin capacity per row (P[deg>=64] ~ 1e-22)

typedef unsigned long long u64;
#define FFMA2(d, a, b, c) \
    asm("fma.rn.f32x2 %0, %1, %2, %3;" : "=l"(d) : "l"(a), "l"(b), "l"(c))

// ---------------- device scratch (no allocations allowed) ----------------
__device__ int    g_cnt[NN];          // per-row edge count
__device__ int2   g_bin[NN * CAP];    // (col, w_bits) per row, padded
__device__ float  g_deg[NN];          // dinv after k_deg2
__device__ float4 g_y[NN * 4];        // y = dinv * x, [N][16]
__device__ float4 g_tx1[NN * 4];      // -dinv[row] * sum(w * y[col]), [N][16]
__device__ float  g_Wc[KF * NG];      // combined gate weights
__device__ float  g_bias[NG];         // bx + bh + bg folded
__device__ float  g_wlin[HIDF];
__device__ float  g_wc2[HIDF];        // peephole for O gate
__device__ float  g_blin;
__device__ int    g_is64;             // edge_index dtype flag

// ---------------- init: detect dtype + fold params + zero counters ----------------
__global__ void k_init(const int* __restrict__ ei32,
                       const float* __restrict__ Wx, const float* __restrict__ bx,
                       const float* __restrict__ bh, const float* __restrict__ wc,
                       const float* __restrict__ bg, const float* __restrict__ Wlin,
                       const float* __restrict__ blin) {
    int gid = blockIdx.x * blockDim.x + threadIdx.x;
    if (gid < NN) g_cnt[gid] = 0;
    if (blockIdx.x != 0) return;
    int t = threadIdx.x;
    if (t == 0) {
        int is64 = 1;
        #pragma unroll
        for (int e = 0; e < 32; e++) {
            if (ei32[2 * e + 1] != 0) { is64 = 0; break; }
        }
        g_is64 = is64;
        g_blin = blin[0];
    }
    for (int idx = t; idx < KF * NG; idx += blockDim.x) {
        int k = idx / NG, o = idx % NG;
        int s = o / HIDF, h = o % HIDF;
        int g = (s == 0) ? 0 : ((s == 1) ? 2 : 3);
        int kk = (k < CINF) ? 0 : 1;
        int kr = k & (CINF - 1);
        g_Wc[idx] = Wx[((g * 2 + kk) * CINF + kr) * HIDF + h];   // Wx: [4][2][CIN][HID]
    }
    for (int idx = t; idx < NG; idx += blockDim.x) {
        int s = idx / HIDF, h = idx % HIDF;
        int g = (s == 0) ? 0 : ((s == 1) ? 2 : 3);
        g_bias[idx] = bx[g * HIDF + h] + bh[g * HIDF + h] + bg[g * HIDF + h];
    }
    if (t < HIDF) {
        g_wlin[t] = Wlin[t];
        g_wc2[t]  = wc[2 * HIDF + t];
    }
}

// ---------------- bin edges: (col, w) into padded per-row bins ----------------
__global__ void __launch_bounds__(256) k_bin(const void* __restrict__ ei,
                                             const float* __restrict__ w) {
    int t = blockIdx.x * 256 + threadIdx.x;           // edges 2t, 2t+1
    if (t >= EE / 2) return;
    int r[2], c[2];
    if (g_is64) {
        longlong2 rr = __ldg(&((const longlong2*)ei)[t]);
        longlong2 cc = __ldg(&((const longlong2*)ei)[EE / 2 + t]);
        r[0] = (int)rr.x; r[1] = (int)rr.y;
        c[0] = (int)cc.x; c[1] = (int)cc.y;
    } else {
        int2 rr = __ldg(&((const int2*)ei)[t]);
        int2 cc = __ldg(&((const int2*)ei)[EE / 2 + t]);
        r[0] = rr.x; r[1] = rr.y;
        c[0] = cc.x; c[1] = cc.y;
    }
    float2 wv = __ldg(&((const float2*)w)[t]);
    float ws[2] = {wv.x, wv.y};
    #pragma unroll
    for (int j = 0; j < 2; j++) {
        int pos = atomicAdd(&g_cnt[r[j]], 1);
        if (pos < CAP)
            g_bin[(r[j] << 6) + pos] = make_int2(c[j], __float_as_int(ws[j]));
    }
}

// ---------------- deg from bins (no atomics), dinv, y = dinv*x ----------------
__global__ void k_deg2(const float* __restrict__ x) {
    int i = blockIdx.x * blockDim.x + threadIdx.x;
    if (i >= NN) return;
    int cnt = min(g_cnt[i], CAP);
    const int2* b = &g_bin[i << 6];
    float s = 0.f;
    for (int j = 0; j < cnt; j++)
        s += __int_as_float(b[j].y);
    float dv = (s > 0.f) ? rsqrtf(s) : 0.f;
    g_deg[i] = dv;
    const float4* x4 = (const float4*)x;
    #pragma unroll
    for (int q = 0; q < 4; q++) {
        float4 v = __ldg(&x4[i * 4 + q]);
        v.x *= dv; v.y *= dv; v.z *= dv; v.w *= dv;
        g_y[i * 4 + q] = v;
    }
}

// ---------------- gather: tx1[row] = -dinv[row] * sum_j w_j * y[col_j] ----------------
// Each thread handles quad q of TWO rows (r, r+NN/2) in one interleaved loop:
// 8 independent y-loads + 4 bin-loads in flight per iteration.
__global__ void __launch_bounds__(256) k_gather() {
    int id = blockIdx.x * 256 + threadIdx.x;
    if (id >= NN * 2) return;
    int q  = id & 3;
    int rp = id >> 2;                 // 0 .. NN/2-1
    int rA = rp, rB = rp + NN / 2;
    int cA = min(g_cnt[rA], CAP), cB = min(g_cnt[rB], CAP);
    const int2* bA = &g_bin[rA << 6];
    const int2* bB = &g_bin[rB << 6];
    float4 aA = make_float4(0.f, 0.f, 0.f, 0.f);
    float4 aB = make_float4(0.f, 0.f, 0.f, 0.f);
    int jm = max(cA, cB);
    for (int j = 0; j < jm; j += 2) {        // j even, j+1 <= CAP-1: reads in-bounds
        int2 eA0 = bA[j], eA1 = bA[j + 1];
        int2 eB0 = bB[j], eB1 = bB[j + 1];
        float wA0 = (j     < cA) ? __int_as_float(eA0.y) : 0.f;
        float wA1 = (j + 1 < cA) ? __int_as_float(eA1.y) : 0.f;
        float wB0 = (j     < cB) ? __int_as_float(eB0.y) : 0.f;
        float wB1 = (j + 1 < cB) ? __int_as_float(eB1.y) : 0.f;
        int iA0 = (j     < cA) ? eA0.x : 0;
        int iA1 = (j + 1 < cA) ? eA1.x : 0;
        int iB0 = (j     < cB) ? eB0.x : 0;
        int iB1 = (j + 1 < cB) ? eB1.x : 0;
        float4 yA0 = g_y[iA0 * 4 + q];
        float4 yA1 = g_y[iA1 * 4 + q];
        float4 yB0 = g_y[iB0 * 4 + q];
        float4 yB1 = g_y[iB1 * 4 + q];
        aA.x = fmaf(wA0, yA0.x, fmaf(wA1, yA1.x, aA.x));
        aA.y = fmaf(wA0, yA0.y, fmaf(wA1, yA1.y, aA.y));
        aA.z = fmaf(wA0, yA0.z, fmaf(wA1, yA1.z, aA.z));
        aA.w = fmaf(wA0, yA0.w, fmaf(wA1, yA1.w, aA.w));
        aB.x = fmaf(wB0, yB0.x, fmaf(wB1, yB1.x, aB.x));
        aB.y = fmaf(wB0, yB0.y, fmaf(wB1, yB1.y, aB.y));
        aB.z = fmaf(wB0, yB0.z, fmaf(wB1, yB1.z, aB.z));
        aB.w = fmaf(wB0, yB0.w, fmaf(wB1, yB1.w, aB.w));
    }
    float sA = -g_deg[rA], sB = -g_deg[rB];
    aA.x *= sA; aA.y *= sA; aA.z *= sA; aA.w *= sA;
    aB.x *= sB; aB.y *= sB; aB.z *= sB; aB.w *= sB;
    g_tx1[(rA << 2) + q] = aA;
    g_tx1[(rB << 2) + q] = aB;
}

// ---------------- dense gates + LSTM + projection (16-node tile, f32x2 FMA) ----------------
// 3 syncs per tile: nonlinearity fused into the warp reduction phase.
__global__ void __launch_bounds__(192) k_gate(const float* __restrict__ x,
                                              float* __restrict__ out) {
    __shared__ __align__(16) float fsm[KF][16];   // [k][node]
    __shared__ float gsm[16 * NG];                // [node][gatecol]

    int t = threadIdx.x;
    float w[KF];
    #pragma unroll
    for (int k = 0; k < KF; k++) w[k] = g_Wc[k * NG + t];
    float bias = g_bias[t];
    u64 biasP;
    asm("mov.b64 %0, {%1, %2};" : "=l"(biasP) : "f"(bias), "f"(bias));
    float blin = g_blin;
    int wid = t >> 5, lane = t & 31;
    float wl0 = g_wlin[lane], wl1 = g_wlin[lane + 32];
    float w20 = g_wc2[lane],  w21 = g_wc2[lane + 32];

    for (int tile = blockIdx.x; tile < NN / 16; tile += gridDim.x) {
        int nbase = tile * 16;
        // ---- load features: 16 nodes x 8 float4 by threads 0..127 ----
        if (t < 128) {
            int j = t >> 3, q = t & 7;
            int node = nbase + j;
            float4 v = (q < 4) ? __ldg(&((const float4*)x)[node * 4 + q])
                               : g_tx1[node * 4 + (q - 4)];
            int k0 = (q < 4) ? q * 4 : 16 + (q - 4) * 4;
            fsm[k0 + 0][j] = v.x;
            fsm[k0 + 1][j] = v.y;
            fsm[k0 + 2][j] = v.z;
            fsm[k0 + 3][j] = v.w;
        }
        __syncthreads();

        // ---- GEMM: 8 node-pairs x 32 k with packed f32x2 FMA ----
        u64 acc[8];
        #pragma unroll
        for (int j = 0; j < 8; j++) acc[j] = biasP;
        #pragma unroll
        for (int k = 0; k < KF; k++) {
            const ulonglong2* fr = (const ulonglong2*)fsm[k];
            ulonglong2 q0 = fr[0], q1 = fr[1], q2 = fr[2], q3 = fr[3];
            u64 wk;
            asm("mov.b64 %0, {%1, %1};" : "=l"(wk) : "f"(w[k]));
            FFMA2(acc[0], q0.x, wk, acc[0]);
            FFMA2(acc[1], q0.y, wk, acc[1]);
            FFMA2(acc[2], q1.x, wk, acc[2]);
            FFMA2(acc[3], q1.y, wk, acc[3]);
            FFMA2(acc[4], q2.x, wk, acc[4]);
            FFMA2(acc[5], q2.y, wk, acc[5]);
            FFMA2(acc[6], q3.x, wk, acc[6]);
            FFMA2(acc[7], q3.y, wk, acc[7]);
        }
        #pragma unroll
        for (int j = 0; j < 8; j++) {
            float lo, hi;
            asm("mov.b64 {%0, %1}, %2;" : "=f"(lo), "=f"(hi) : "l"(acc[j]));
            gsm[(2 * j) * NG + t]     = lo;
            gsm[(2 * j + 1) * NG + t] = hi;
        }
        __syncthreads();

        // ---- fused nonlinearity + reduction: warp wid -> nodes wid, wid+6, wid+12 ----
        for (int n = wid; n < 16; n += 6) {
            const float* g = &gsm[n * NG];
            float gi0 = g[lane],        gi1 = g[lane + 32];
            float gc0 = g[64 + lane],   gc1 = g[96 + lane];
            float go0 = g[128 + lane],  go1 = g[160 + lane];
            float I0 = fmaf(0.5f, __tanhf(0.5f * gi0), 0.5f);
            float I1 = fmaf(0.5f, __tanhf(0.5f * gi1), 0.5f);
            float C0 = I0 * __tanhf(gc0);
            float C1 = I1 * __tanhf(gc1);
            float O0 = fmaf(0.5f, __tanhf(0.5f * fmaf(w20, C0, go0)), 0.5f);
            float O1 = fmaf(0.5f, __tanhf(0.5f * fmaf(w21, C1, go1)), 0.5f);
            float p = fmaf(O0 * __tanhf(C0), wl0, O1 * __tanhf(C1) * wl1);
            #pragma unroll
            for (int off = 16; off > 0; off >>= 1)
                p += __shfl_xor_sync(0xffffffffu, p, off);
            if (lane == 0) out[nbase + n] = p + blin;
        }
        __syncthreads();
    }
}

// ---------------- launch ----------------
extern "C" void kernel_launch(void* const* d_in, const int* in_sizes, int n_in,
                              void* d_out, int out_size) {
    const float* x    = (const float*)d_in[0];
    const void*  ei   = d_in[1];
    const float* w    = (const float*)d_in[2];
    const float* Wx   = (const float*)d_in[3];
    const float* bx   = (const float*)d_in[4];
    // d_in[5] = Wh: provably unused (H0 = 0)
    const float* bh   = (const float*)d_in[6];
    const float* wc   = (const float*)d_in[7];
    const float* bg   = (const float*)d_in[8];
    const float* Wlin = (const float*)d_in[9];
    const float* blin = (const float*)d_in[10];
    float* out = (float*)d_out;

    k_init<<<(NN + 255) / 256, 256>>>((const int*)ei, Wx, bx, bh, wc, bg, Wlin, blin);
    k_bin<<<(EE / 2 + 255) / 256, 256>>>(ei, w);
    k_deg2<<<(NN + 255) / 256, 256>>>(x);
    k_gather<<<(NN * 2 + 255) / 256, 256>>>();
    k_gate<<<3125, 192>>>(x, out);   // exactly 2 tiles per block
}

// round 9
// speedup vs baseline: 1.0617x; 1.0617x over previous
#include <cuda_runtime.h>

#define NN   100000
#define EE   1600000
#define CINF 16
#define HIDF 64
#define NG   192      // 3 live gates (i, c, o) x 64
#define KF   32       // feature dim: [x(16) | tx1(16)]
#define CAP  64       // bin capacity per row (P[deg>=64] ~ 1e-22)

typedef unsigned long long u64;
#define FFMA2(d, a, b, c) \
    asm("fma.rn.f32x2 %0, %1, %2, %3;" : "=l"(d) : "l"(a), "l"(b), "l"(c))

// ---------------- device scratch (no allocations allowed) ----------------
__device__ int    g_cnt[NN];          // per-row edge count
__device__ int2   g_bin[NN * CAP];    // (col, w_bits) per row, padded
__device__ float  g_deg[NN];          // dinv after k_deg2
__device__ float4 g_y[NN * 4];        // y = dinv * x, [N][16]
__device__ float4 g_tx1[NN * 4];      // -dinv[row] * sum(w * y[col]), [N][16]
__device__ float  g_Wc[KF * NG];      // combined gate weights
__device__ float  g_bias[NG];         // bx + bh + bg folded
__device__ float  g_wlin[HIDF];
__device__ float  g_wc2[HIDF];        // peephole for O gate
__device__ float  g_blin;
__device__ int    g_is64;             // edge_index dtype flag

// ---------------- init: detect dtype + fold params + zero counters ----------------
__global__ void k_init(const int* __restrict__ ei32,
                       const float* __restrict__ Wx, const float* __restrict__ bx,
                       const float* __restrict__ bh, const float* __restrict__ wc,
                       const float* __restrict__ bg, const float* __restrict__ Wlin,
                       const float* __restrict__ blin) {
    int gid = blockIdx.x * blockDim.x + threadIdx.x;
    if (gid < NN) g_cnt[gid] = 0;
    if (blockIdx.x != 0) return;
    int t = threadIdx.x;
    if (t == 0) {
        int is64 = 1;
        #pragma unroll
        for (int e = 0; e < 32; e++) {
            if (ei32[2 * e + 1] != 0) { is64 = 0; break; }
        }
        g_is64 = is64;
        g_blin = blin[0];
    }
    for (int idx = t; idx < KF * NG; idx += blockDim.x) {
        int k = idx / NG, o = idx % NG;
        int s = o / HIDF, h = o % HIDF;
        int g = (s == 0) ? 0 : ((s == 1) ? 2 : 3);
        int kk = (k < CINF) ? 0 : 1;
        int kr = k & (CINF - 1);
        g_Wc[idx] = Wx[((g * 2 + kk) * CINF + kr) * HIDF + h];   // Wx: [4][2][CIN][HID]
    }
    for (int idx = t; idx < NG; idx += blockDim.x) {
        int s = idx / HIDF, h = idx % HIDF;
        int g = (s == 0) ? 0 : ((s == 1) ? 2 : 3);
        g_bias[idx] = bx[g * HIDF + h] + bh[g * HIDF + h] + bg[g * HIDF + h];
    }
    if (t < HIDF) {
        g_wlin[t] = Wlin[t];
        g_wc2[t]  = wc[2 * HIDF + t];
    }
}

// ---------------- bin edges: (col, w) into padded per-row bins (4 edges/thread) ----------------
__global__ void __launch_bounds__(256) k_bin(const void* __restrict__ ei,
                                             const float* __restrict__ w) {
    int t = blockIdx.x * 256 + threadIdx.x;           // edges 4t..4t+3
    if (t >= EE / 4) return;
    int r[4], c[4];
    if (g_is64) {
        longlong2 r0 = __ldg(&((const longlong2*)ei)[2 * t]);
        longlong2 r1 = __ldg(&((const longlong2*)ei)[2 * t + 1]);
        longlong2 c0 = __ldg(&((const longlong2*)ei)[EE / 2 + 2 * t]);
        longlong2 c1 = __ldg(&((const longlong2*)ei)[EE / 2 + 2 * t + 1]);
        r[0] = (int)r0.x; r[1] = (int)r0.y; r[2] = (int)r1.x; r[3] = (int)r1.y;
        c[0] = (int)c0.x; c[1] = (int)c0.y; c[2] = (int)c1.x; c[3] = (int)c1.y;
    } else {
        int4 rr = __ldg(&((const int4*)ei)[t]);
        int4 cc = __ldg(&((const int4*)ei)[EE / 4 + t]);
        r[0] = rr.x; r[1] = rr.y; r[2] = rr.z; r[3] = rr.w;
        c[0] = cc.x; c[1] = cc.y; c[2] = cc.z; c[3] = cc.w;
    }
    float4 wv = __ldg(&((const float4*)w)[t]);
    float ws[4] = {wv.x, wv.y, wv.z, wv.w};
    #pragma unroll
    for (int j = 0; j < 4; j++) {
        int pos = atomicAdd(&g_cnt[r[j]], 1);
        if (pos < CAP)
            g_bin[(r[j] << 6) + pos] = make_int2(c[j], __float_as_int(ws[j]));
    }
}

// ---------------- deg from bins (no atomics), dinv, y = dinv*x ----------------
__global__ void k_deg2(const float* __restrict__ x) {
    int i = blockIdx.x * blockDim.x + threadIdx.x;
    if (i >= NN) return;
    int cnt = min(g_cnt[i], CAP);
    const int2* b = &g_bin[i << 6];
    float s = 0.f;
    for (int j = 0; j < cnt; j++)
        s += __int_as_float(b[j].y);
    float dv = (s > 0.f) ? rsqrtf(s) : 0.f;
    g_deg[i] = dv;
    const float4* x4 = (const float4*)x;
    #pragma unroll
    for (int q = 0; q < 4; q++) {
        float4 v = __ldg(&x4[i * 4 + q]);
        v.x *= dv; v.y *= dv; v.z *= dv; v.w *= dv;
        g_y[i * 4 + q] = v;
    }
}

// ---------------- gather: tx1[row] = -dinv[row] * sum_j w_j * y[col_j] ----------------
// 4 threads per row, one float4 quad each; y reads are 64B-coalesced per group.
__global__ void __launch_bounds__(256) k_gather() {
    int id = blockIdx.x * 256 + threadIdx.x;
    if (id >= NN * 4) return;
    int row = id >> 2, q = id & 3;
    int cnt = min(g_cnt[row], CAP);
    const int2* b = &g_bin[row << 6];
    float4 acc = make_float4(0.f, 0.f, 0.f, 0.f);
    int j = 0;
    for (; j + 4 <= cnt; j += 4) {
        int2 e0 = __ldg(&b[j]),     e1 = __ldg(&b[j + 1]);
        int2 e2 = __ldg(&b[j + 2]), e3 = __ldg(&b[j + 3]);
        float w0 = __int_as_float(e0.y), w1 = __int_as_float(e1.y);
        float w2 = __int_as_float(e2.y), w3 = __int_as_float(e3.y);
        float4 y0 = g_y[e0.x * 4 + q];
        float4 y1 = g_y[e1.x * 4 + q];
        float4 y2 = g_y[e2.x * 4 + q];
        float4 y3 = g_y[e3.x * 4 + q];
        acc.x = fmaf(w0, y0.x, fmaf(w1, y1.x, fmaf(w2, y2.x, fmaf(w3, y3.x, acc.x))));
        acc.y = fmaf(w0, y0.y, fmaf(w1, y1.y, fmaf(w2, y2.y, fmaf(w3, y3.y, acc.y))));
        acc.z = fmaf(w0, y0.z, fmaf(w1, y1.z, fmaf(w2, y2.z, fmaf(w3, y3.z, acc.z))));
        acc.w = fmaf(w0, y0.w, fmaf(w1, y1.w, fmaf(w2, y2.w, fmaf(w3, y3.w, acc.w))));
    }
    for (; j < cnt; j++) {
        int2 e0 = __ldg(&b[j]);
        float w0 = __int_as_float(e0.y);
        float4 y0 = g_y[e0.x * 4 + q];
        acc.x = fmaf(w0, y0.x, acc.x);
        acc.y = fmaf(w0, y0.y, acc.y);
        acc.z = fmaf(w0, y0.z, acc.z);
        acc.w = fmaf(w0, y0.w, acc.w);
    }
    float s = -g_deg[row];
    acc.x *= s; acc.y *= s; acc.z *= s; acc.w *= s;
    g_tx1[(row << 2) + q] = acc;
}

// ---------------- dense gates + LSTM + projection (16-node tile, f32x2 FMA) ----------------
// 3 syncs per tile: nonlinearity fused into the warp reduction phase.
__global__ void __launch_bounds__(192) k_gate(const float* __restrict__ x,
                                              float* __restrict__ out) {
    __shared__ __align__(16) float fsm[KF][16];   // [k][node]
    __shared__ float gsm[16 * NG];                // [node][gatecol]

    int t = threadIdx.x;
    float w[KF];
    #pragma unroll
    for (int k = 0; k < KF; k++) w[k] = g_Wc[k * NG + t];
    float bias = g_bias[t];
    u64 biasP;
    asm("mov.b64 %0, {%1, %2};" : "=l"(biasP) : "f"(bias), "f"(bias));
    float blin = g_blin;
    int wid = t >> 5, lane = t & 31;
    float wl0 = g_wlin[lane], wl1 = g_wlin[lane + 32];
    float w20 = g_wc2[lane],  w21 = g_wc2[lane + 32];

    for (int tile = blockIdx.x; tile < NN / 16; tile += gridDim.x) {
        int nbase = tile * 16;
        // ---- load features: 16 nodes x 8 float4 by threads 0..127 ----
        if (t < 128) {
            int j = t >> 3, q = t & 7;
            int node = nbase + j;
            float4 v = (q < 4) ? __ldg(&((const float4*)x)[node * 4 + q])
                               : g_tx1[node * 4 + (q - 4)];
            int k0 = (q < 4) ? q * 4 : 16 + (q - 4) * 4;
            fsm[k0 + 0][j] = v.x;
            fsm[k0 + 1][j] = v.y;
            fsm[k0 + 2][j] = v.z;
            fsm[k0 + 3][j] = v.w;
        }
        __syncthreads();

        // ---- GEMM: 8 node-pairs x 32 k with packed f32x2 FMA ----
        u64 acc[8];
        #pragma unroll
        for (int j = 0; j < 8; j++) acc[j] = biasP;
        #pragma unroll
        for (int k = 0; k < KF; k++) {
            const ulonglong2* fr = (const ulonglong2*)fsm[k];
            ulonglong2 q0 = fr[0], q1 = fr[1], q2 = fr[2], q3 = fr[3];
            u64 wk;
            asm("mov.b64 %0, {%1, %1};" : "=l"(wk) : "f"(w[k]));
            FFMA2(acc[0], q0.x, wk, acc[0]);
            FFMA2(acc[1], q0.y, wk, acc[1]);
            FFMA2(acc[2], q1.x, wk, acc[2]);
            FFMA2(acc[3], q1.y, wk, acc[3]);
            FFMA2(acc[4], q2.x, wk, acc[4]);
            FFMA2(acc[5], q2.y, wk, acc[5]);
            FFMA2(acc[6], q3.x, wk, acc[6]);
            FFMA2(acc[7], q3.y, wk, acc[7]);
        }
        #pragma unroll
        for (int j = 0; j < 8; j++) {
            float lo, hi;
            asm("mov.b64 {%0, %1}, %2;" : "=f"(lo), "=f"(hi) : "l"(acc[j]));
            gsm[(2 * j) * NG + t]     = lo;
            gsm[(2 * j + 1) * NG + t] = hi;
        }
        __syncthreads();

        // ---- fused nonlinearity + reduction: warp wid -> nodes wid, wid+6, wid+12 ----
        for (int n = wid; n < 16; n += 6) {
            const float* g = &gsm[n * NG];
            float gi0 = g[lane],        gi1 = g[lane + 32];
            float gc0 = g[64 + lane],   gc1 = g[96 + lane];
            float go0 = g[128 + lane],  go1 = g[160 + lane];
            float I0 = fmaf(0.5f, __tanhf(0.5f * gi0), 0.5f);
            float I1 = fmaf(0.5f, __tanhf(0.5f * gi1), 0.5f);
            float C0 = I0 * __tanhf(gc0);
            float C1 = I1 * __tanhf(gc1);
            float O0 = fmaf(0.5f, __tanhf(0.5f * fmaf(w20, C0, go0)), 0.5f);
            float O1 = fmaf(0.5f, __tanhf(0.5f * fmaf(w21, C1, go1)), 0.5f);
            float p = fmaf(O0 * __tanhf(C0), wl0, O1 * __tanhf(C1) * wl1);
            #pragma unroll
            for (int off = 16; off > 0; off >>= 1)
                p += __shfl_xor_sync(0xffffffffu, p, off);
            if (lane == 0) out[nbase + n] = p + blin;
        }
        __syncthreads();
    }
}

// ---------------- launch ----------------
extern "C" void kernel_launch(void* const* d_in, const int* in_sizes, int n_in,
                              void* d_out, int out_size) {
    const float* x    = (const float*)d_in[0];
    const void*  ei   = d_in[1];
    const float* w    = (const float*)d_in[2];
    const float* Wx   = (const float*)d_in[3];
    const float* bx   = (const float*)d_in[4];
    // d_in[5] = Wh: provably unused (H0 = 0)
    const float* bh   = (const float*)d_in[6];
    const float* wc   = (const float*)d_in[7];
    const float* bg   = (const float*)d_in[8];
    const float* Wlin = (const float*)d_in[9];
    const float* blin = (const float*)d_in[10];
    float* out = (float*)d_out;

    k_init<<<(NN + 255) / 256, 256>>>((const int*)ei, Wx, bx, bh, wc, bg, Wlin, blin);
    k_bin<<<(EE / 4 + 255) / 256, 256>>>(ei, w);
    k_deg2<<<(NN + 255) / 256, 256>>>(x);
    k_gather<<<(NN * 4 + 255) / 256, 256>>>();
    k_gate<<<3125, 192>>>(x, out);   // exactly 2 tiles per block
}

// round 10
// speedup vs baseline: 1.0642x; 1.0024x over previous
#include <cuda_runtime.h>

#define NN   100000
#define EE   1600000
#define CINF 16
#define HIDF 64
#define NG   192      // 3 live gates (i, c, o) x 64
#define KF   32       // feature dim: [x(16) | tx1(16)]
#define CAP  64       // bin capacity per row (P[deg>=64] ~ 1e-22)
#define TN   32       // nodes per gate tile

typedef unsigned long long u64;
#define FFMA2(d, a, b, c) \
    asm("fma.rn.f32x2 %0, %1, %2, %3;" : "=l"(d) : "l"(a), "l"(b), "l"(c))

// ---------------- device scratch (no allocations allowed) ----------------
__device__ int    g_cnt[NN];          // per-row edge count
__device__ int2   g_bin[NN * CAP];    // (col, w_bits) per row, padded
__device__ float  g_deg[NN];          // dinv after k_deg2
__device__ float4 g_y[NN * 4];        // y = dinv * x, [N][16]
__device__ float4 g_tx1[NN * 4];      // -dinv[row] * sum(w * y[col]), [N][16]
__device__ float  g_Wc[KF * NG];      // combined gate weights
__device__ float  g_bias[NG];         // bx + bh + bg folded
__device__ float  g_wlin[HIDF];
__device__ float  g_wc2[HIDF];        // peephole for O gate
__device__ float  g_blin;
__device__ int    g_is64;             // edge_index dtype flag

// ---------------- init: detect dtype + fold params + zero counters ----------------
__global__ void k_init(const int* __restrict__ ei32,
                       const float* __restrict__ Wx, const float* __restrict__ bx,
                       const float* __restrict__ bh, const float* __restrict__ wc,
                       const float* __restrict__ bg, const float* __restrict__ Wlin,
                       const float* __restrict__ blin) {
    int gid = blockIdx.x * blockDim.x + threadIdx.x;
    if (gid < NN) g_cnt[gid] = 0;
    if (blockIdx.x != 0) return;
    int t = threadIdx.x;
    if (t == 0) {
        int is64 = 1;
        #pragma unroll
        for (int e = 0; e < 32; e++) {
            if (ei32[2 * e + 1] != 0) { is64 = 0; break; }
        }
        g_is64 = is64;
        g_blin = blin[0];
    }
    for (int idx = t; idx < KF * NG; idx += blockDim.x) {
        int k = idx / NG, o = idx % NG;
        int s = o / HIDF, h = o % HIDF;
        int g = (s == 0) ? 0 : ((s == 1) ? 2 : 3);
        int kk = (k < CINF) ? 0 : 1;
        int kr = k & (CINF - 1);
        g_Wc[idx] = Wx[((g * 2 + kk) * CINF + kr) * HIDF + h];   // Wx: [4][2][CIN][HID]
    }
    for (int idx = t; idx < NG; idx += blockDim.x) {
        int s = idx / HIDF, h = idx % HIDF;
        int g = (s == 0) ? 0 : ((s == 1) ? 2 : 3);
        g_bias[idx] = bx[g * HIDF + h] + bh[g * HIDF + h] + bg[g * HIDF + h];
    }
    if (t < HIDF) {
        g_wlin[t] = Wlin[t];
        g_wc2[t]  = wc[2 * HIDF + t];
    }
}

// ---------------- bin edges: (col, w) into padded per-row bins (4 edges/thread) ----------------
__global__ void __launch_bounds__(256) k_bin(const void* __restrict__ ei,
                                             const float* __restrict__ w) {
    int t = blockIdx.x * 256 + threadIdx.x;           // edges 4t..4t+3
    if (t >= EE / 4) return;
    int r[4], c[4];
    if (g_is64) {
        longlong2 r0 = __ldg(&((const longlong2*)ei)[2 * t]);
        longlong2 r1 = __ldg(&((const longlong2*)ei)[2 * t + 1]);
        longlong2 c0 = __ldg(&((const longlong2*)ei)[EE / 2 + 2 * t]);
        longlong2 c1 = __ldg(&((const longlong2*)ei)[EE / 2 + 2 * t + 1]);
        r[0] = (int)r0.x; r[1] = (int)r0.y; r[2] = (int)r1.x; r[3] = (int)r1.y;
        c[0] = (int)c0.x; c[1] = (int)c0.y; c[2] = (int)c1.x; c[3] = (int)c1.y;
    } else {
        int4 rr = __ldg(&((const int4*)ei)[t]);
        int4 cc = __ldg(&((const int4*)ei)[EE / 4 + t]);
        r[0] = rr.x; r[1] = rr.y; r[2] = rr.z; r[3] = rr.w;
        c[0] = cc.x; c[1] = cc.y; c[2] = cc.z; c[3] = cc.w;
    }
    float4 wv = __ldg(&((const float4*)w)[t]);
    float ws[4] = {wv.x, wv.y, wv.z, wv.w};
    #pragma unroll
    for (int j = 0; j < 4; j++) {
        int pos = atomicAdd(&g_cnt[r[j]], 1);
        if (pos < CAP)
            g_bin[(r[j] << 6) + pos] = make_int2(c[j], __float_as_int(ws[j]));
    }
}

// ---------------- deg from bins (no atomics), dinv, y = dinv*x ----------------
__global__ void k_deg2(const float* __restrict__ x) {
    int i = blockIdx.x * blockDim.x + threadIdx.x;
    if (i >= NN) return;
    int cnt = min(g_cnt[i], CAP);
    const int2* b = &g_bin[i << 6];
    float s = 0.f;
    for (int j = 0; j < cnt; j++)
        s += __int_as_float(b[j].y);
    float dv = (s > 0.f) ? rsqrtf(s) : 0.f;
    g_deg[i] = dv;
    const float4* x4 = (const float4*)x;
    #pragma unroll
    for (int q = 0; q < 4; q++) {
        float4 v = __ldg(&x4[i * 4 + q]);
        v.x *= dv; v.y *= dv; v.z *= dv; v.w *= dv;
        g_y[i * 4 + q] = v;
    }
}

// ---------------- gather: tx1[row] = -dinv[row] * sum_j w_j * y[col_j] ----------------
// 4 threads per row, one float4 quad each; y reads are 64B-coalesced per group.
__global__ void __launch_bounds__(256) k_gather() {
    int id = blockIdx.x * 256 + threadIdx.x;
    if (id >= NN * 4) return;
    int row = id >> 2, q = id & 3;
    int cnt = min(g_cnt[row], CAP);
    const int2* b = &g_bin[row << 6];
    float4 acc = make_float4(0.f, 0.f, 0.f, 0.f);
    int j = 0;
    for (; j + 4 <= cnt; j += 4) {
        int2 e0 = __ldg(&b[j]),     e1 = __ldg(&b[j + 1]);
        int2 e2 = __ldg(&b[j + 2]), e3 = __ldg(&b[j + 3]);
        float w0 = __int_as_float(e0.y), w1 = __int_as_float(e1.y);
        float w2 = __int_as_float(e2.y), w3 = __int_as_float(e3.y);
        float4 y0 = g_y[e0.x * 4 + q];
        float4 y1 = g_y[e1.x * 4 + q];
        float4 y2 = g_y[e2.x * 4 + q];
        float4 y3 = g_y[e3.x * 4 + q];
        acc.x = fmaf(w0, y0.x, fmaf(w1, y1.x, fmaf(w2, y2.x, fmaf(w3, y3.x, acc.x))));
        acc.y = fmaf(w0, y0.y, fmaf(w1, y1.y, fmaf(w2, y2.y, fmaf(w3, y3.y, acc.y))));
        acc.z = fmaf(w0, y0.z, fmaf(w1, y1.z, fmaf(w2, y2.z, fmaf(w3, y3.z, acc.z))));
        acc.w = fmaf(w0, y0.w, fmaf(w1, y1.w, fmaf(w2, y2.w, fmaf(w3, y3.w, acc.w))));
    }
    for (; j < cnt; j++) {
        int2 e0 = __ldg(&b[j]);
        float w0 = __int_as_float(e0.y);
        float4 y0 = g_y[e0.x * 4 + q];
        acc.x = fmaf(w0, y0.x, acc.x);
        acc.y = fmaf(w0, y0.y, acc.y);
        acc.z = fmaf(w0, y0.z, acc.z);
        acc.w = fmaf(w0, y0.w, acc.w);
    }
    float s = -g_deg[row];
    acc.x *= s; acc.y *= s; acc.z *= s; acc.w *= s;
    g_tx1[(row << 2) + q] = acc;
}

// ---------------- dense gates + LSTM + projection (32-node tile, one per block) ----------------
__global__ void __launch_bounds__(192) k_gate(const float* __restrict__ x,
                                              float* __restrict__ out) {
    __shared__ __align__(16) float fsm[KF][TN];   // [k][node]  4KB
    __shared__ float gsm[TN * NG];                // [node][gatecol] 24KB

    int t = threadIdx.x;
    float w[KF];
    #pragma unroll
    for (int k = 0; k < KF; k++) w[k] = g_Wc[k * NG + t];
    float bias = g_bias[t];
    u64 biasP;
    asm("mov.b64 %0, {%1, %2};" : "=l"(biasP) : "f"(bias), "f"(bias));
    float blin = g_blin;
    int wid = t >> 5, lane = t & 31;
    float wl0 = g_wlin[lane], wl1 = g_wlin[lane + 32];
    float w20 = g_wc2[lane],  w21 = g_wc2[lane + 32];

    int nbase = blockIdx.x * TN;

    // ---- load features: 32 nodes x 8 float4 = 256 tasks over 192 threads ----
    #pragma unroll
    for (int it = 0; it < 2; it++) {
        int id = t + it * 192;
        if (id < TN * 8) {
            int j = id >> 3, q = id & 7;
            int node = nbase + j;
            float4 v = (q < 4) ? __ldg(&((const float4*)x)[node * 4 + q])
                               : g_tx1[node * 4 + (q - 4)];
            int k0 = (q < 4) ? q * 4 : 16 + (q - 4) * 4;
            fsm[k0 + 0][j] = v.x;
            fsm[k0 + 1][j] = v.y;
            fsm[k0 + 2][j] = v.z;
            fsm[k0 + 3][j] = v.w;
        }
    }
    __syncthreads();

    // ---- GEMM: 16 node-pairs x 32 k with packed f32x2 FMA ----
    u64 acc[16];
    #pragma unroll
    for (int j = 0; j < 16; j++) acc[j] = biasP;
    #pragma unroll
    for (int k = 0; k < KF; k++) {
        const ulonglong2* fr = (const ulonglong2*)fsm[k];
        u64 wk;
        asm("mov.b64 %0, {%1, %1};" : "=l"(wk) : "f"(w[k]));
        #pragma unroll
        for (int h = 0; h < 8; h++) {
            ulonglong2 qq = fr[h];
            FFMA2(acc[2 * h],     qq.x, wk, acc[2 * h]);
            FFMA2(acc[2 * h + 1], qq.y, wk, acc[2 * h + 1]);
        }
    }
    #pragma unroll
    for (int j = 0; j < 16; j++) {
        float lo, hi;
        asm("mov.b64 {%0, %1}, %2;" : "=f"(lo), "=f"(hi) : "l"(acc[j]));
        gsm[(2 * j) * NG + t]     = lo;
        gsm[(2 * j + 1) * NG + t] = hi;
    }
    __syncthreads();

    // ---- fused nonlinearity + reduction: warp wid -> nodes wid, wid+6, ... ----
    for (int n = wid; n < TN; n += 6) {
        const float* g = &gsm[n * NG];
        float gi0 = g[lane],        gi1 = g[lane + 32];
        float gc0 = g[64 + lane],   gc1 = g[96 + lane];
        float go0 = g[128 + lane],  go1 = g[160 + lane];
        float I0 = fmaf(0.5f, __tanhf(0.5f * gi0), 0.5f);
        float I1 = fmaf(0.5f, __tanhf(0.5f * gi1), 0.5f);
        float C0 = I0 * __tanhf(gc0);
        float C1 = I1 * __tanhf(gc1);
        float O0 = fmaf(0.5f, __tanhf(0.5f * fmaf(w20, C0, go0)), 0.5f);
        float O1 = fmaf(0.5f, __tanhf(0.5f * fmaf(w21, C1, go1)), 0.5f);
        float p = fmaf(O0 * __tanhf(C0), wl0, O1 * __tanhf(C1) * wl1);
        #pragma unroll
        for (int off = 16; off > 0; off >>= 1)
            p += __shfl_xor_sync(0xffffffffu, p, off);
        if (lane == 0) out[nbase + n] = p + blin;
    }
}

// ---------------- launch ----------------
extern "C" void kernel_launch(void* const* d_in, const int* in_sizes, int n_in,
                              void* d_out, int out_size) {
    const float* x    = (const float*)d_in[0];
    const void*  ei   = d_in[1];
    const float* w    = (const float*)d_in[2];
    const float* Wx   = (const float*)d_in[3];
    const float* bx   = (const float*)d_in[4];
    // d_in[5] = Wh: provably unused (H0 = 0)
    const float* bh   = (const float*)d_in[6];
    const float* wc   = (const float*)d_in[7];
    const float* bg   = (const float*)d_in[8];
    const float* Wlin = (const float*)d_in[9];
    const float* blin = (const float*)d_in[10];
    float* out = (float*)d_out;

    k_init<<<(NN + 255) / 256, 256>>>((const int*)ei, Wx, bx, bh, wc, bg, Wlin, blin);
    k_bin<<<(EE / 4 + 255) / 256, 256>>>(ei, w);
    k_deg2<<<(NN + 255) / 256, 256>>>(x);
    k_gather<<<(NN * 4 + 255) / 256, 256>>>();
    k_gate<<<NN / TN, 192>>>(x, out);   // 3125 blocks, one 32-node tile each
}

// round 12
// speedup vs baseline: 1.0854x; 1.0198x over previous
#include <cuda_runtime.h>

#define NN   100000
#define EE   1600000
#define CINF 16
#define HIDF 64
#define NG   192      // 3 live gates (i, c, o) x 64
#define KF   32       // feature dim: [x(16) | tx1(16)]
#define CAP  64       // bin capacity per row (P[deg>=64] ~ 1e-22)
#define TN   32       // nodes per gate tile

typedef unsigned long long u64;
#define FFMA2(d, a, b, c) \
    asm("fma.rn.f32x2 %0, %1, %2, %3;" : "=l"(d) : "l"(a), "l"(b), "l"(c))

// ---------------- device scratch (no allocations allowed) ----------------
// g_cnt: zero-initialized at module load (.bss); k_gate re-zeroes it each run
// so every graph replay starts from cnt=0.
__device__ int    g_cnt[NN];          // per-row edge count
__device__ int2   g_bin[NN * CAP];    // (col, w_bits) per row, padded
__device__ float  g_deg[NN];          // dinv after k_deg2
__device__ float4 g_y[NN * 4];        // y = dinv * x, [N][16]
__device__ float4 g_tx1[NN * 4];      // -dinv[row] * sum(w * y[col]), [N][16]
__device__ float  g_Wc[KF * NG];      // combined gate weights
__device__ float  g_bias[NG];         // bx + bh + bg folded
__device__ float  g_wlin[HIDF];
__device__ float  g_wc2[HIDF];        // peephole for O gate
__device__ float  g_blin;

// ---------------- bin edges: (col, w) into padded per-row bins (4 edges/thread) ----------------
__global__ void __launch_bounds__(256) k_bin(const void* __restrict__ ei,
                                             const float* __restrict__ w) {
    __shared__ int s_is64;
    if (threadIdx.x == 0) {
        int is64 = 1;
        const int* e32 = (const int*)ei;
        #pragma unroll
        for (int e = 0; e < 32; e++) {
            if (e32[2 * e + 1] != 0) { is64 = 0; break; }
        }
        s_is64 = is64;
    }
    __syncthreads();
    int t = blockIdx.x * 256 + threadIdx.x;           // edges 4t..4t+3
    if (t >= EE / 4) return;
    int r[4], c[4];
    if (s_is64) {
        longlong2 r0 = __ldg(&((const longlong2*)ei)[2 * t]);
        longlong2 r1 = __ldg(&((const longlong2*)ei)[2 * t + 1]);
        longlong2 c0 = __ldg(&((const longlong2*)ei)[EE / 2 + 2 * t]);
        longlong2 c1 = __ldg(&((const longlong2*)ei)[EE / 2 + 2 * t + 1]);
        r[0] = (int)r0.x; r[1] = (int)r0.y; r[2] = (int)r1.x; r[3] = (int)r1.y;
        c[0] = (int)c0.x; c[1] = (int)c0.y; c[2] = (int)c1.x; c[3] = (int)c1.y;
    } else {
        int4 rr = __ldg(&((const int4*)ei)[t]);
        int4 cc = __ldg(&((const int4*)ei)[EE / 4 + t]);
        r[0] = rr.x; r[1] = rr.y; r[2] = rr.z; r[3] = rr.w;
        c[0] = cc.x; c[1] = cc.y; c[2] = cc.z; c[3] = cc.w;
    }
    float4 wv = __ldg(&((const float4*)w)[t]);
    float ws[4] = {wv.x, wv.y, wv.z, wv.w};
    #pragma unroll
    for (int j = 0; j < 4; j++) {
        int pos = atomicAdd(&g_cnt[r[j]], 1);
        if (pos < CAP)
            g_bin[(r[j] << 6) + pos] = make_int2(c[j], __float_as_int(ws[j]));
    }
}

// ---------------- deg from bins, dinv, y = dinv*x;  block 0 also folds params ----------------
__global__ void k_deg2(const float* __restrict__ x,
                       const float* __restrict__ Wx, const float* __restrict__ bx,
                       const float* __restrict__ bh, const float* __restrict__ wc,
                       const float* __restrict__ bg, const float* __restrict__ Wlin,
                       const float* __restrict__ blin) {
    int i = blockIdx.x * blockDim.x + threadIdx.x;
    if (blockIdx.x == 0) {
        int t = threadIdx.x;
        for (int idx = t; idx < KF * NG; idx += blockDim.x) {
            int k = idx / NG, o = idx % NG;
            int s = o / HIDF, h = o % HIDF;
            int g = (s == 0) ? 0 : ((s == 1) ? 2 : 3);
            int kk = (k < CINF) ? 0 : 1;
            int kr = k & (CINF - 1);
            g_Wc[idx] = Wx[((g * 2 + kk) * CINF + kr) * HIDF + h];   // Wx: [4][2][CIN][HID]
        }
        for (int idx = t; idx < NG; idx += blockDim.x) {
            int s = idx / HIDF, h = idx % HIDF;
            int g = (s == 0) ? 0 : ((s == 1) ? 2 : 3);
            g_bias[idx] = bx[g * HIDF + h] + bh[g * HIDF + h] + bg[g * HIDF + h];
        }
        if (t < HIDF) {
            g_wlin[t] = Wlin[t];
            g_wc2[t]  = wc[2 * HIDF + t];
        }
        if (t == 0) g_blin = blin[0];
    }
    if (i >= NN) return;
    int cnt = min(g_cnt[i], CAP);
    const int2* b = &g_bin[i << 6];
    float s = 0.f;
    for (int j = 0; j < cnt; j++)
        s += __int_as_float(b[j].y);
    float dv = (s > 0.f) ? rsqrtf(s) : 0.f;
    g_deg[i] = dv;
    const float4* x4 = (const float4*)x;
    #pragma unroll
    for (int q = 0; q < 4; q++) {
        float4 v = __ldg(&x4[i * 4 + q]);
        v.x *= dv; v.y *= dv; v.z *= dv; v.w *= dv;
        g_y[i * 4 + q] = v;
    }
}

// ---------------- gather: tx1[row] = -dinv[row] * sum_j w_j * y[col_j] ----------------
// 4 threads per row, one float4 quad each; y reads are 64B-coalesced per group.
__global__ void __launch_bounds__(256) k_gather() {
    int id = blockIdx.x * 256 + threadIdx.x;
    if (id >= NN * 4) return;
    int row = id >> 2, q = id & 3;
    int cnt = min(g_cnt[row], CAP);
    const int2* b = &g_bin[row << 6];
    float4 acc = make_float4(0.f, 0.f, 0.f, 0.f);
    int j = 0;
    for (; j + 4 <= cnt; j += 4) {
        int2 e0 = __ldg(&b[j]),     e1 = __ldg(&b[j + 1]);
        int2 e2 = __ldg(&b[j + 2]), e3 = __ldg(&b[j + 3]);
        float w0 = __int_as_float(e0.y), w1 = __int_as_float(e1.y);
        float w2 = __int_as_float(e2.y), w3 = __int_as_float(e3.y);
        float4 y0 = g_y[e0.x * 4 + q];
        float4 y1 = g_y[e1.x * 4 + q];
        float4 y2 = g_y[e2.x * 4 + q];
        float4 y3 = g_y[e3.x * 4 + q];
        acc.x = fmaf(w0, y0.x, fmaf(w1, y1.x, fmaf(w2, y2.x, fmaf(w3, y3.x, acc.x))));
        acc.y = fmaf(w0, y0.y, fmaf(w1, y1.y, fmaf(w2, y2.y, fmaf(w3, y3.y, acc.y))));
        acc.z = fmaf(w0, y0.z, fmaf(w1, y1.z, fmaf(w2, y2.z, fmaf(w3, y3.z, acc.z))));
        acc.w = fmaf(w0, y0.w, fmaf(w1, y1.w, fmaf(w2, y2.w, fmaf(w3, y3.w, acc.w))));
    }
    for (; j < cnt; j++) {
        int2 e0 = __ldg(&b[j]);
        float w0 = __int_as_float(e0.y);
        float4 y0 = g_y[e0.x * 4 + q];
        acc.x = fmaf(w0, y0.x, acc.x);
        acc.y = fmaf(w0, y0.y, acc.y);
        acc.z = fmaf(w0, y0.z, acc.z);
        acc.w = fmaf(w0, y0.w, acc.w);
    }
    float s = -g_deg[row];
    acc.x *= s; acc.y *= s; acc.z *= s; acc.w *= s;
    g_tx1[(row << 2) + q] = acc;
}

// ---------------- dense gates + LSTM + projection (32-node tile, one per block) ----------------
// Also resets g_cnt for the next graph replay (coalesced, 32 ints per block).
__global__ void __launch_bounds__(192) k_gate(const float* __restrict__ x,
                                              float* __restrict__ out) {
    __shared__ __align__(16) float fsm[KF][TN];   // [k][node]  4KB
    __shared__ float gsm[TN * NG];                // [node][gatecol] 24KB

    int t = threadIdx.x;
    int nbase = blockIdx.x * TN;
    if (t < TN) g_cnt[nbase + t] = 0;             // reset for next replay

    float w[KF];
    #pragma unroll
    for (int k = 0; k < KF; k++) w[k] = g_Wc[k * NG + t];
    float bias = g_bias[t];
    u64 biasP;
    asm("mov.b64 %0, {%1, %2};" : "=l"(biasP) : "f"(bias), "f"(bias));
    float blin = g_blin;
    int wid = t >> 5, lane = t & 31;
    float wl0 = g_wlin[lane], wl1 = g_wlin[lane + 32];
    float w20 = g_wc2[lane],  w21 = g_wc2[lane + 32];

    // ---- load features: 32 nodes x 8 float4 = 256 tasks over 192 threads ----
    #pragma unroll
    for (int it = 0; it < 2; it++) {
        int id = t + it * 192;
        if (id < TN * 8) {
            int j = id >> 3, q = id & 7;
            int node = nbase + j;
            float4 v = (q < 4) ? __ldg(&((const float4*)x)[node * 4 + q])
                               : g_tx1[node * 4 + (q - 4)];
            int k0 = (q < 4) ? q * 4 : 16 + (q - 4) * 4;
            fsm[k0 + 0][j] = v.x;
            fsm[k0 + 1][j] = v.y;
            fsm[k0 + 2][j] = v.z;
            fsm[k0 + 3][j] = v.w;
        }
    }
    __syncthreads();

    // ---- GEMM: 16 node-pairs x 32 k with packed f32x2 FMA ----
    u64 acc[16];
    #pragma unroll
    for (int j = 0; j < 16; j++) acc[j] = biasP;
    #pragma unroll
    for (int k = 0; k < KF; k++) {
        const ulonglong2* fr = (const ulonglong2*)fsm[k];
        u64 wk;
        asm("mov.b64 %0, {%1, %1};" : "=l"(wk) : "f"(w[k]));
        #pragma unroll
        for (int h = 0; h < 8; h++) {
            ulonglong2 qq = fr[h];
            FFMA2(acc[2 * h],     qq.x, wk, acc[2 * h]);
            FFMA2(acc[2 * h + 1], qq.y, wk, acc[2 * h + 1]);
        }
    }
    #pragma unroll
    for (int j = 0; j < 16; j++) {
        float lo, hi;
        asm("mov.b64 {%0, %1}, %2;" : "=f"(lo), "=f"(hi) : "l"(acc[j]));
        gsm[(2 * j) * NG + t]     = lo;
        gsm[(2 * j + 1) * NG + t] = hi;
    }
    __syncthreads();

    // ---- fused nonlinearity + reduction: warp wid -> nodes wid, wid+6, ... ----
    for (int n = wid; n < TN; n += 6) {
        const float* g = &gsm[n * NG];
        float gi0 = g[lane],        gi1 = g[lane + 32];
        float gc0 = g[64 + lane],   gc1 = g[96 + lane];
        float go0 = g[128 + lane],  go1 = g[160 + lane];
        float I0 = fmaf(0.5f, __tanhf(0.5f * gi0), 0.5f);
        float I1 = fmaf(0.5f, __tanhf(0.5f * gi1), 0.5f);
        float C0 = I0 * __tanhf(gc0);
        float C1 = I1 * __tanhf(gc1);
        float O0 = fmaf(0.5f, __tanhf(0.5f * fmaf(w20, C0, go0)), 0.5f);
        float O1 = fmaf(0.5f, __tanhf(0.5f * fmaf(w21, C1, go1)), 0.5f);
        float p = fmaf(O0 * __tanhf(C0), wl0, O1 * __tanhf(C1) * wl1);
        #pragma unroll
        for (int off = 16; off > 0; off >>= 1)
            p += __shfl_xor_sync(0xffffffffu, p, off);
        if (lane == 0) out[nbase + n] = p + blin;
    }
}

// ---------------- launch ----------------
extern "C" void kernel_launch(void* const* d_in, const int* in_sizes, int n_in,
                              void* d_out, int out_size) {
    const float* x    = (const float*)d_in[0];
    const void*  ei   = d_in[1];
    const float* w    = (const float*)d_in[2];
    const float* Wx   = (const float*)d_in[3];
    const float* bx   = (const float*)d_in[4];
    // d_in[5] = Wh: provably unused (H0 = 0)
    const float* bh   = (const float*)d_in[6];
    const float* wc   = (const float*)d_in[7];
    const float* bg   = (const float*)d_in[8];
    const float* Wlin = (const float*)d_in[9];
    const float* blin = (const float*)d_in[10];
    float* out = (float*)d_out;

    k_bin<<<(EE / 4 + 255) / 256, 256>>>(ei, w);
    k_deg2<<<(NN + 255) / 256, 256>>>(x, Wx, bx, bh, wc, bg, Wlin, blin);
    k_gather<<<(NN * 4 + 255) / 256, 256>>>();
    k_gate<<<NN / TN, 192>>>(x, out);   // 3125 blocks; also resets g_cnt
}